// round 12
// baseline (speedup 1.0000x reference)
#include <cuda_runtime.h>
#include <cuda_bf16.h>
#include <cuda_fp8.h>
#include <math.h>
#include <stdint.h>

#define NN   8192
#define DEG  8
#define NH   4
#define NF   768
#define NHD  3072
#define ND   768
#define NBG  8
#define NPG  1024
#define NQ   16
#define NROW 128   // NBG*NQ

// ---------------- scratch (static device memory; no allocation) ----------------
__device__ __nv_bfloat16 g_feat16[(size_t)NN * NHD];
__device__ __nv_bfloat16 g_h16[(size_t)NN * NHD];
__device__ __nv_fp8_e4m3 g_a8[(size_t)NN * NHD];
__device__ __nv_fp8_e4m3 g_bT8[(size_t)NHD * NHD];
__device__ float g_el[NN * NH];
__device__ float g_er[NN * NH];
__device__ float g_m1[(size_t)NN * NF];
__device__ float g_rep[(size_t)NN * NF];
__device__ float g_S[(size_t)NROW * NN];
__device__ float g_colsum[NHD];
__device__ float g_colsq[NHD];
__device__ float g_colA[NHD];
__device__ float g_colB[NHD];

// ================= fp8 tensor-core GEMM (m16n8k32 e4m3 + ldmatrix) =================
// Block tile 128x256x64(fp8), 256 threads = 8 warps (2m x 4n), warp tile 64x64.
// 3-stage cp.async pipeline. 1 CTA/SM (launch_bounds 256,1; ~185 regs, no spill).
// L2 traffic: 768 CTAs x (128+256)x3072 B = 0.9 GB (was 1.2 GB at 128x128).
#define BK8   64
#define AROWS 128
#define BROWS 256
#define STAGE_B ((AROWS + BROWS) * 80)          // bytes per stage = 30720
#define GEMM_SMEM (3 * STAGE_B)                 // 92160 B

__device__ __forceinline__ void cp_async16(void* dst, const void* src) {
    unsigned int s = (unsigned int)__cvta_generic_to_shared(dst);
    asm volatile("cp.async.cg.shared.global [%0], [%1], 16;" :: "r"(s), "l"(src));
}

#define LDSM4(r0, r1, r2, r3, addr) \
    asm volatile("ldmatrix.sync.aligned.m8n8.x4.shared.b16 {%0,%1,%2,%3}, [%4];" \
        : "=r"(r0), "=r"(r1), "=r"(r2), "=r"(r3) : "r"(addr))

__device__ __forceinline__ void fp8_load_tiles(
    char* smem, const __nv_fp8_e4m3* Ab, const __nv_fp8_e4m3* Bb,
    int stage, int k0, int tid, int K)
{
    char* As = smem + stage * STAGE_B;
    char* Bs = As + AROWS * 80;
#pragma unroll
    for (int i = 0; i < 2; i++) {
        int li = tid + i * 256;          // 0..511: A, 128 rows x 4 chunks
        int r = li >> 2, ch = li & 3;
        cp_async16(As + r * 80 + ch * 16, Ab + (size_t)r * K + k0 + ch * 16);
    }
#pragma unroll
    for (int i = 0; i < 4; i++) {
        int li = tid + i * 256;          // 0..1023: B, 256 rows x 4 chunks
        int r = li >> 2, ch = li & 3;
        cp_async16(Bs + r * 80 + ch * 16, Bb + (size_t)r * K + k0 + ch * 16);
    }
    asm volatile("cp.async.commit_group;");
}

__global__ void __launch_bounds__(256, 1) fp8_gemm_kernel(
    const __nv_fp8_e4m3* __restrict__ A, const __nv_fp8_e4m3* __restrict__ Bt,
    __nv_bfloat16* __restrict__ C, int K,
    const float* __restrict__ al, const float* __restrict__ ar,
    float* __restrict__ el, float* __restrict__ er)
{
    extern __shared__ char smem[];
    int tid = threadIdx.x;
    int lane = tid & 31, wid = tid >> 5;
    int wm = (wid & 1) * 64, wn = (wid >> 1) * 64;
    int g = lane >> 2, tig = lane & 3;
    const __nv_fp8_e4m3* Ab = A + (size_t)blockIdx.y * 128 * K;
    const __nv_fp8_e4m3* Bb = Bt + (size_t)blockIdx.x * 256 * K;

    unsigned sbase = (unsigned)__cvta_generic_to_shared(smem);
    unsigned aoff = (unsigned)((wm + (lane & 15)) * 80 + (lane >> 4) * 16);
    unsigned boff = (unsigned)((wn + ((lane >> 4) & 1) * 8 + (lane & 7)) * 80
                               + ((lane >> 3) & 1) * 16);

    float c[4][8][4];
#pragma unroll
    for (int mt = 0; mt < 4; mt++)
#pragma unroll
        for (int nt = 0; nt < 8; nt++)
#pragma unroll
            for (int i = 0; i < 4; i++) c[mt][nt][i] = 0.f;

    int nk = K / BK8;
    fp8_load_tiles(smem, Ab, Bb, 0, 0, tid, K);
    if (nk > 1) fp8_load_tiles(smem, Ab, Bb, 1, BK8, tid, K);
    if (nk > 2) fp8_load_tiles(smem, Ab, Bb, 2, 2 * BK8, tid, K);

    for (int t = 0; t < nk; t++) {
        asm volatile("cp.async.wait_group 2;" ::: "memory");
        __syncthreads();
        int stage = t % 3;
        unsigned sa = sbase + (unsigned)(stage * STAGE_B);
        unsigned sb = sa + (unsigned)(AROWS * 80);
#pragma unroll
        for (int kk2 = 0; kk2 < 2; kk2++) {
            unsigned a[4][4], b[8][2];
#pragma unroll
            for (int mt = 0; mt < 4; mt++)
                LDSM4(a[mt][0], a[mt][1], a[mt][2], a[mt][3],
                      sa + aoff + (unsigned)(mt * 16 * 80 + kk2 * 32));
#pragma unroll
            for (int ntp = 0; ntp < 4; ntp++)
                LDSM4(b[ntp * 2][0], b[ntp * 2][1], b[ntp * 2 + 1][0], b[ntp * 2 + 1][1],
                      sb + boff + (unsigned)(ntp * 16 * 80 + kk2 * 32));
#pragma unroll
            for (int mt = 0; mt < 4; mt++)
#pragma unroll
                for (int nt = 0; nt < 8; nt++)
                    asm volatile(
                        "mma.sync.aligned.m16n8k32.row.col.f32.e4m3.e4m3.f32 "
                        "{%0,%1,%2,%3}, {%4,%5,%6,%7}, {%8,%9}, {%0,%1,%2,%3};"
                        : "+f"(c[mt][nt][0]), "+f"(c[mt][nt][1]),
                          "+f"(c[mt][nt][2]), "+f"(c[mt][nt][3])
                        : "r"(a[mt][0]), "r"(a[mt][1]), "r"(a[mt][2]), "r"(a[mt][3]),
                          "r"(b[nt][0]), "r"(b[nt][1]));
        }
        __syncthreads();
        if (t + 3 < nk)
            fp8_load_tiles(smem, Ab, Bb, (t + 3) % 3, (t + 3) * BK8, tid, K);
    }

    // ---- epilogue: bf16 store + fused el/er partial dots ----
    __nv_bfloat16* Cb = C + (size_t)(blockIdx.y * 128) * NHD + blockIdx.x * 256;
    float pel[8], per[8];
#pragma unroll
    for (int i = 0; i < 8; i++) { pel[i] = 0.f; per[i] = 0.f; }
#pragma unroll
    for (int nt = 0; nt < 8; nt++) {
        int colg = blockIdx.x * 256 + wn + nt * 8 + 2 * tig;
        float a0 = al[colg], a1 = al[colg + 1];
        float r0 = ar[colg], r1 = ar[colg + 1];
#pragma unroll
        for (int mt = 0; mt < 4; mt++) {
            int row = wm + mt * 16 + g;
            int col = wn + nt * 8 + 2 * tig;
            *(__nv_bfloat162*)(Cb + (size_t)row * NHD + col) =
                __floats2bfloat162_rn(c[mt][nt][0], c[mt][nt][1]);
            *(__nv_bfloat162*)(Cb + (size_t)(row + 8) * NHD + col) =
                __floats2bfloat162_rn(c[mt][nt][2], c[mt][nt][3]);
            pel[mt * 2]     += c[mt][nt][0] * a0 + c[mt][nt][1] * a1;
            pel[mt * 2 + 1] += c[mt][nt][2] * a0 + c[mt][nt][3] * a1;
            per[mt * 2]     += c[mt][nt][0] * r0 + c[mt][nt][1] * r1;
            per[mt * 2 + 1] += c[mt][nt][2] * r0 + c[mt][nt][3] * r1;
        }
    }
#pragma unroll
    for (int off = 1; off <= 2; off <<= 1)
#pragma unroll
        for (int i = 0; i < 8; i++) {
            pel[i] += __shfl_xor_sync(0xffffffffu, pel[i], off);
            per[i] += __shfl_xor_sync(0xffffffffu, per[i], off);
        }
    if (tig == 0) {
        int hd = (blockIdx.x * 256) / NF;   // 768 = 3*256: tile never crosses heads
#pragma unroll
        for (int mt = 0; mt < 4; mt++)
#pragma unroll
            for (int hf = 0; hf < 2; hf++) {
                int n = blockIdx.y * 128 + wm + mt * 16 + hf * 8 + g;
                atomicAdd(&el[n * NH + hd], pel[mt * 2 + hf]);
                atomicAdd(&er[n * NH + hd], per[mt * 2 + hf]);
            }
    }
}

// ---------------- fp32 -> fp8 convert ----------------
__global__ void cvt8_kernel(const float* __restrict__ x, __nv_fp8_e4m3* __restrict__ o, int n) {
    int i = blockIdx.x * 256 + threadIdx.x;
    if (i < n) o[i] = __nv_fp8_e4m3(x[i]);
}

// ---------------- W[K][M] -> Bt[M][K] fp8 transpose ----------------
__global__ __launch_bounds__(256) void wtrans_kernel(
    const float* __restrict__ W, __nv_fp8_e4m3* __restrict__ Bt, int K, int M)
{
    __shared__ float t[32][33];
    int m0 = blockIdx.x * 32, k0 = blockIdx.y * 32;
    int tx = threadIdx.x & 31, ty = threadIdx.x >> 5;
#pragma unroll
    for (int i = 0; i < 32; i += 8)
        t[ty + i][tx] = W[(size_t)(k0 + ty + i) * M + m0 + tx];
    __syncthreads();
#pragma unroll
    for (int i = 0; i < 32; i += 8)
        Bt[(size_t)(m0 + ty + i) * K + k0 + tx] = __nv_fp8_e4m3(t[tx][ty + i]);
}

// ---------------- per-layer zeroing ----------------
__global__ void prep_kernel() {
    int i = blockIdx.x * 256 + threadIdx.x;
    if (i < NHD) { g_colsum[i] = 0.f; g_colsq[i] = 0.f; }
    if (i < NN * NH) { g_el[i] = 0.f; g_er[i] = 0.f; }
}

// ---------------- edge softmax + aggregation (+bias), bf16 ----------------
__global__ __launch_bounds__(256) void aggregate_kernel(
    const __nv_bfloat16* __restrict__ feat, const float* __restrict__ el,
    const float* __restrict__ er, const int* __restrict__ esrc,
    const float* __restrict__ bias, __nv_bfloat16* __restrict__ outh)
{
    int n = blockIdx.x;
    __shared__ int   ssrc[DEG];
    __shared__ float salpha[NH * DEG];
    int tid = threadIdx.x;
    if (tid < DEG) ssrc[tid] = esrc[n * DEG + tid];
    __syncthreads();
    if (tid < 32) {
        int h = tid >> 3, k = tid & 7;
        float e = el[ssrc[k] * NH + h] + er[n * NH + h];
        e = e > 0.f ? e : 0.2f * e;
        float m = e;
#pragma unroll
        for (int o = 4; o; o >>= 1) m = fmaxf(m, __shfl_xor_sync(0xffffffffu, m, o));
        float a = __expf(e - m);
        float s = a;
#pragma unroll
        for (int o = 4; o; o >>= 1) s += __shfl_xor_sync(0xffffffffu, s, o);
        salpha[tid] = a / s;
    }
    __syncthreads();
    const __nv_bfloat162* f2 = (const __nv_bfloat162*)feat;
    __nv_bfloat162* o2 = (__nv_bfloat162*)outh;
    for (int c2 = tid; c2 < NHD / 2; c2 += 256) {
        int h = c2 / (NF / 2);
        float accx = bias[2 * c2], accy = bias[2 * c2 + 1];
#pragma unroll
        for (int k = 0; k < DEG; k++) {
            float w = salpha[h * DEG + k];
            float2 v = __bfloat1622float2(f2[(size_t)ssrc[k] * (NHD / 2) + c2]);
            accx += w * v.x; accy += w * v.y;
        }
        o2[(size_t)n * (NHD / 2) + c2] = __floats2bfloat162_rn(accx, accy);
    }
}

// ---------------- column stats ----------------
__global__ __launch_bounds__(256) void colstats_kernel(const __nv_bfloat16* __restrict__ x) {
    int c2 = blockIdx.x * 256 + threadIdx.x;
    int r0 = blockIdx.y * 256;
    const __nv_bfloat162* x2 = (const __nv_bfloat162*)x;
    float s0 = 0.f, s1 = 0.f, q0 = 0.f, q1 = 0.f;
    for (int r = r0; r < r0 + 256; r++) {
        float2 v = __bfloat1622float2(x2[(size_t)r * (NHD / 2) + c2]);
        s0 += v.x; q0 += v.x * v.x;
        s1 += v.y; q1 += v.y * v.y;
    }
    atomicAdd(&g_colsum[2 * c2], s0);
    atomicAdd(&g_colsum[2 * c2 + 1], s1);
    atomicAdd(&g_colsq[2 * c2], q0);
    atomicAdd(&g_colsq[2 * c2 + 1], q1);
}

__global__ void colfin_kernel(const float* __restrict__ gamma, const float* __restrict__ beta) {
    int c = blockIdx.x * 256 + threadIdx.x;
    if (c >= NHD) return;
    float mu  = g_colsum[c] * (1.f / NN);
    float var = g_colsq[c] * (1.f / NN) - mu * mu;
    float rs  = rsqrtf(var + 1e-5f);
    float a   = rs * gamma[c];
    g_colA[c] = a;
    g_colB[c] = beta[c] - mu * a;
}

// ---------------- LN + PReLU epilogues ----------------
__global__ __launch_bounds__(256) void lnfuse1_kernel(
    const __nv_bfloat16* __restrict__ h, const float* __restrict__ pa,
    __nv_fp8_e4m3* __restrict__ a8, float* __restrict__ m1)
{
    int n = blockIdx.x;
    for (int f = threadIdx.x; f < NF; f += 256) {
        float s = 0.f;
#pragma unroll
        for (int hh = 0; hh < 4; hh++) {
            int c = hh * NF + f;
            float y = g_colA[c] * __bfloat162float(h[(size_t)n * NHD + c]) + g_colB[c];
            y = y > 0.f ? y : pa[c] * y;
            a8[(size_t)n * NHD + c] = __nv_fp8_e4m3(y);
            s += y;
        }
        m1[(size_t)n * NF + f] = 0.25f * s;
    }
}

__global__ __launch_bounds__(256) void lnfuse2_kernel(
    const __nv_bfloat16* __restrict__ h, const float* __restrict__ pa)
{
    int n = blockIdx.x;
    for (int f = threadIdx.x; f < NF; f += 256) {
        float s = 0.f;
#pragma unroll
        for (int hh = 0; hh < 4; hh++) {
            int c = hh * NF + f;
            float y = g_colA[c] * __bfloat162float(h[(size_t)n * NHD + c]) + g_colB[c];
            y = y > 0.f ? y : pa[c] * y;
            s += y;
        }
        g_rep[(size_t)n * NF + f] = fmaxf(g_m1[(size_t)n * NF + f], 0.25f * s);
    }
}

// ---------------- sims: S[128 x 8192] = Qe @ rep^T ----------------
__global__ __launch_bounds__(256) void simgemm_kernel(
    const float* __restrict__ Qe, const float* __restrict__ R)
{
    __shared__ float Qs[128][33];
    __shared__ float Rs[32][33];
    int tid = threadIdx.x;
    int n0 = blockIdx.x * 32;
    float acc[16];
#pragma unroll
    for (int i = 0; i < 16; i++) acc[i] = 0.f;
    int n = tid & 31, rb = tid >> 5;

    for (int k0 = 0; k0 < ND; k0 += 32) {
#pragma unroll
        for (int t = 0; t < 16; t++) {
            int li = tid + t * 256;
            Qs[li >> 5][li & 31] = Qe[(size_t)(li >> 5) * ND + k0 + (li & 31)];
        }
#pragma unroll
        for (int t = 0; t < 4; t++) {
            int li = tid + t * 256;
            Rs[li >> 5][li & 31] = R[(size_t)(n0 + (li >> 5)) * ND + k0 + (li & 31)];
        }
        __syncthreads();
#pragma unroll
        for (int kk = 0; kk < 32; kk++) {
            float b = Rs[n][kk];
#pragma unroll
            for (int i = 0; i < 16; i++)
                acc[i] += Qs[rb + 8 * i][kk] * b;
        }
        __syncthreads();
    }
#pragma unroll
    for (int i = 0; i < 16; i++)
        g_S[(size_t)(rb + 8 * i) * NN + n0 + n] = acc[i];
}

// ---------------- output zero ----------------
__global__ void zeroout_kernel(float* out) {
    if (threadIdx.x < 3) out[threadIdx.x] = 0.f;
}

// ---------------- losses ----------------
__device__ __forceinline__ float warpSumF(float v) {
#pragma unroll
    for (int o = 16; o; o >>= 1) v += __shfl_xor_sync(0xffffffffu, v, o);
    return v;
}

__device__ __forceinline__ float blockSumF(float v, float* sred, int tid) {
    v = warpSumF(v);
    if ((tid & 31) == 0) sred[tid >> 5] = v;
    __syncthreads();
    if (tid < 32) {
        float x = (tid < 16) ? sred[tid] : 0.f;
        x = warpSumF(x);
        if (tid == 0) sred[0] = x;
    }
    __syncthreads();
    float r = sred[0];
    __syncthreads();
    return r;
}

__device__ __forceinline__ float blockMaxF(float v, float* sred, int tid) {
#pragma unroll
    for (int o = 16; o; o >>= 1) v = fmaxf(v, __shfl_xor_sync(0xffffffffu, v, o));
    if ((tid & 31) == 0) sred[tid >> 5] = v;
    __syncthreads();
    if (tid < 32) {
        float x = (tid < 16) ? sred[tid] : -INFINITY;
#pragma unroll
        for (int o = 16; o; o >>= 1) x = fmaxf(x, __shfl_xor_sync(0xffffffffu, x, o));
        if (tid == 0) sred[0] = x;
    }
    __syncthreads();
    float r = sred[0];
    __syncthreads();
    return r;
}

__device__ void bitonic1024_desc(float* key, int* idx, int tid) {
    for (int k = 2; k <= 1024; k <<= 1) {
        for (int j = k >> 1; j > 0; j >>= 1) {
#pragma unroll 1
            for (int t = tid; t < 1024; t += 512) {
                int x = t ^ j;
                if (x > t) {
                    bool descSeg = ((t & k) == 0);
                    float ka = key[t], kb = key[x];
                    int   ia = idx[t], ib = idx[x];
                    bool aFirst = (ka > kb) || (ka == kb && ia < ib);
                    bool doSwap = descSeg ? (!aFirst) : aFirst;
                    if (doSwap) { key[t] = kb; key[x] = ka; idx[t] = ib; idx[x] = ia; }
                }
            }
            __syncthreads();
        }
    }
}

// lambda-MRR via product trick (no per-pair MUFU).
__global__ __launch_bounds__(512) void loss_kernel(const float* __restrict__ bert, float* __restrict__ out) {
    __shared__ float skey[1024];
    __shared__ int   sidx[1024];
    __shared__ float sez[1024];
    __shared__ float sred[16];
    __shared__ float sh_psim;
    int r = blockIdx.x;
    int g = r >> 4;
    int base = g * NPG;
    int tid = threadIdx.x;
    const float* Srow = g_S + (size_t)r * NN;

    skey[tid]       = bert[(size_t)r * NPG + tid];       sidx[tid]       = tid;
    skey[tid + 512] = bert[(size_t)r * NPG + tid + 512]; sidx[tid + 512] = tid + 512;
    __syncthreads();
    bitonic1024_desc(skey, sidx, tid);

    int i0 = sidx[tid], i1 = sidx[tid + 512];
    float v0 = Srow[base + i0], v1 = Srow[base + i1];
    __syncthreads();
    skey[tid] = v0;       sidx[tid] = tid;
    skey[tid + 512] = v1; sidx[tid + 512] = tid + 512;
    if (tid == 0) sh_psim = v0;
    __syncthreads();

    bitonic1024_desc(skey, sidx, tid);

    {
        float y0 = skey[0];
        sez[tid]       = __expf(fmaxf(skey[tid]       - y0, -60.f));
        sez[tid + 512] = __expf(fmaxf(skey[tid + 512] - y0, -60.f));
    }
    __syncthreads();

    int wid = tid >> 5, lane = tid & 31;
    float uacc = 0.f, tacc = 0.f;
#pragma unroll 1
    for (int half = 0; half < 2; half++) {
        int c = half ? (31 - wid) : wid;
        int i = c * 32 + lane;
        float yi = skey[i];
        int   pi = sidx[i];
        float inv = __fdividef(1.f, sez[i]);
        float ts0 = 0.f, ts1 = 0.f, ts2 = 0.f, ts3 = 0.f;
#pragma unroll 1
        for (int jb = c * 32; jb < 1024; jb += 32) {
            float p0 = 1.f, p1 = 1.f, p2 = 1.f, p3 = 1.f;
#pragma unroll
            for (int q4 = 0; q4 < 8; q4++) {
                int j4 = jb + q4 * 4;
                float4 y4 = *(const float4*)&skey[j4];
                float4 e4 = *(const float4*)&sez[j4];
                int4   p4 = *(const int4*)&sidx[j4];
                {   bool act = (j4 + 0) > i;
                    p0 *= act ? fmaf(e4.x, inv, 1.f) : 1.f;
                    float t = fminf(yi - y4.x, 50.f);
                    if (act && pi > p4.x) ts0 += t; }
                {   bool act = (j4 + 1) > i;
                    p1 *= act ? fmaf(e4.y, inv, 1.f) : 1.f;
                    float t = fminf(yi - y4.y, 50.f);
                    if (act && pi > p4.y) ts1 += t; }
                {   bool act = (j4 + 2) > i;
                    p2 *= act ? fmaf(e4.z, inv, 1.f) : 1.f;
                    float t = fminf(yi - y4.z, 50.f);
                    if (act && pi > p4.z) ts2 += t; }
                {   bool act = (j4 + 3) > i;
                    p3 *= act ? fmaf(e4.w, inv, 1.f) : 1.f;
                    float t = fminf(yi - y4.w, 50.f);
                    if (act && pi > p4.w) ts3 += t; }
            }
            uacc += __logf((p0 * p1) * (p2 * p3));
        }
        tacc += (ts0 + ts1) + (ts2 + ts3);
    }
    float Ltot = blockSumF(uacc + tacc, sred, tid);

    float mx = -INFINITY;
    for (int c = tid; c < NN; c += 512) mx = fmaxf(mx, Srow[c]);
    float m = blockMaxF(mx, sred, tid);

    float se = 0.f, s1 = 0.f, s2 = 0.f;
    for (int c = tid; c < NN; c += 512) {
        float x = Srow[c] - m;
        float e = __expf(x);
        se += e;
        if (c >= base && c < base + NPG) { s1 += e; s2 += x * e; }
    }
    se = blockSumF(se, sred, tid);
    s1 = blockSumF(s1, sred, tid);
    s2 = blockSumF(s2, sred, tid);

    if (tid == 0) {
        float lse = m + __logf(se);
        float cl  = lse - sh_psim;
        float ent = __logf(s1) - s2 / s1;
        atomicAdd(out + 0, cl  * (1.f / 128.f));
        atomicAdd(out + 2, ent * (1.f / 128.f));
        atomicAdd(out + 1, Ltot * (1.f / 67043328.f));
    }
}

// ---------------- launch ----------------
extern "C" void kernel_launch(void* const* d_in, const int* in_sizes, int n_in,
                              void* d_out, int out_size) {
    const float* x      = (const float*)d_in[0];
    const int*   esrc   = (const int*)d_in[1];
    const float* qe     = (const float*)d_in[3];
    const float* bert   = (const float*)d_in[4];
    const float* W1     = (const float*)d_in[5];
    const float* al1    = (const float*)d_in[6];
    const float* ar1    = (const float*)d_in[7];
    const float* b1     = (const float*)d_in[8];
    const float* gamma1 = (const float*)d_in[9];
    const float* beta1  = (const float*)d_in[10];
    const float* pa1    = (const float*)d_in[11];
    const float* W2     = (const float*)d_in[12];
    const float* al2    = (const float*)d_in[13];
    const float* ar2    = (const float*)d_in[14];
    const float* b2     = (const float*)d_in[15];
    const float* gamma2 = (const float*)d_in[16];
    const float* beta2  = (const float*)d_in[17];
    const float* pa2    = (const float*)d_in[18];
    float* out = (float*)d_out;

    float *el, *er, *m1, *rep;
    __nv_bfloat16 *feat16, *h16;
    __nv_fp8_e4m3 *a8, *bT8;
    cudaGetSymbolAddress((void**)&feat16, g_feat16);
    cudaGetSymbolAddress((void**)&h16,    g_h16);
    cudaGetSymbolAddress((void**)&el,     g_el);
    cudaGetSymbolAddress((void**)&er,     g_er);
    cudaGetSymbolAddress((void**)&m1,     g_m1);
    cudaGetSymbolAddress((void**)&rep,    g_rep);
    cudaGetSymbolAddress((void**)&a8,     g_a8);
    cudaGetSymbolAddress((void**)&bT8,    g_bT8);

    cudaFuncSetAttribute(fp8_gemm_kernel,
                         cudaFuncAttributeMaxDynamicSharedMemorySize, GEMM_SMEM);

    dim3 gGemm(NHD / 256, NN / 128);       // (12, 64)
    dim3 gStats(NHD / 512, NN / 256);      // (6, 32)

    // ---- layer 1 (ordered so the ncu -s5 slot lands on fp8_gemm_kernel) ----
    cvt8_kernel<<<(NN * ND + 255) / 256, 256>>>(x, a8, NN * ND);
    wtrans_kernel<<<dim3(NHD / 32, ND / 32), 256>>>(W1, bT8, ND, NHD);
    prep_kernel<<<(NN * NH + 255) / 256, 256>>>();
    fp8_gemm_kernel<<<gGemm, 256, GEMM_SMEM>>>(a8, bT8, feat16, ND, al1, ar1, el, er);
    aggregate_kernel<<<NN, 256>>>(feat16, el, er, esrc, b1, h16);
    colstats_kernel<<<gStats, 256>>>(h16);
    colfin_kernel<<<NHD / 256, 256>>>(gamma1, beta1);
    lnfuse1_kernel<<<NN, 256>>>(h16, pa1, a8, m1);

    // ---- layer 2 ----
    wtrans_kernel<<<dim3(NHD / 32, NHD / 32), 256>>>(W2, bT8, NHD, NHD);
    prep_kernel<<<(NN * NH + 255) / 256, 256>>>();
    fp8_gemm_kernel<<<gGemm, 256, GEMM_SMEM>>>(a8, bT8, feat16, NHD, al2, ar2, el, er);
    aggregate_kernel<<<NN, 256>>>(feat16, el, er, esrc, b2, h16);
    colstats_kernel<<<gStats, 256>>>(h16);
    colfin_kernel<<<NHD / 256, 256>>>(gamma2, beta2);
    lnfuse2_kernel<<<NN, 256>>>(h16, pa2);

    // ---- similarities + losses ----
    simgemm_kernel<<<NN / 32, 256>>>(qe, rep);
    zeroout_kernel<<<1, 32>>>(out);
    loss_kernel<<<NROW, 512>>>(bert, out);
}

// round 13
// speedup vs baseline: 1.1264x; 1.1264x over previous
#include <cuda_runtime.h>
#include <cuda_bf16.h>
#include <cuda_fp8.h>
#include <math.h>
#include <stdint.h>

#define NN   8192
#define DEG  8
#define NH   4
#define NF   768
#define NHD  3072
#define ND   768
#define NBG  8
#define NPG  1024
#define NQ   16
#define NROW 128   // NBG*NQ

// ---------------- scratch (static device memory; no allocation) ----------------
__device__ __nv_bfloat16 g_feat16[(size_t)NN * NHD];
__device__ __nv_bfloat16 g_h16[(size_t)NN * NHD];
__device__ __nv_fp8_e4m3 g_a8[(size_t)NN * NHD];
__device__ __nv_fp8_e4m3 g_bT8[(size_t)NHD * NHD];
__device__ float g_el[NN * NH];
__device__ float g_er[NN * NH];
__device__ float g_m1[(size_t)NN * NF];
__device__ float g_rep[(size_t)NN * NF];
__device__ float g_S[(size_t)NROW * NN];
__device__ float g_colsum[NHD];
__device__ float g_colsq[NHD];
__device__ float g_colA[NHD];
__device__ float g_colB[NHD];

// ================= fp8 tensor-core GEMM (m16n8k32 e4m3 + ldmatrix) =================
// Block tile 128x128x64(fp8), 256 threads = 8 warps (2m x 4n), warp tile 64x32.
// 3-STAGE cp.async pipeline (wait_group 1: each load gets 2 compute periods).
// launch_bounds(256,2): ~110 regs -> 2 CTAs/SM = 16 warps/SM (proven R11 shape).
#define BK8   64
#define STAGE_B (256 * 80)            // (128 A rows + 128 B rows) x 80 B = 20480
#define GEMM_SMEM (3 * STAGE_B)       // 61440 B; x2 CTAs = 120 KB/SM

__device__ __forceinline__ void cp_async16(void* dst, const void* src) {
    unsigned int s = (unsigned int)__cvta_generic_to_shared(dst);
    asm volatile("cp.async.cg.shared.global [%0], [%1], 16;" :: "r"(s), "l"(src));
}

#define LDSM4(r0, r1, r2, r3, addr) \
    asm volatile("ldmatrix.sync.aligned.m8n8.x4.shared.b16 {%0,%1,%2,%3}, [%4];" \
        : "=r"(r0), "=r"(r1), "=r"(r2), "=r"(r3) : "r"(addr))

__device__ __forceinline__ void fp8_load_tiles(
    char* smem, const __nv_fp8_e4m3* Ab, const __nv_fp8_e4m3* Bb,
    int stage, int k0, int tid, int K)
{
    char* As = smem + stage * STAGE_B;
    char* Bs = As + 128 * 80;
#pragma unroll
    for (int i = 0; i < 2; i++) {
        int li = tid + i * 256;          // A: 128 rows x 4 16B-chunks
        int r = li >> 2, ch = li & 3;
        cp_async16(As + r * 80 + ch * 16, Ab + (size_t)r * K + k0 + ch * 16);
    }
#pragma unroll
    for (int i = 0; i < 2; i++) {
        int li = tid + i * 256;          // B: 128 rows x 4 16B-chunks
        int r = li >> 2, ch = li & 3;
        cp_async16(Bs + r * 80 + ch * 16, Bb + (size_t)r * K + k0 + ch * 16);
    }
}

__global__ void __launch_bounds__(256, 2) fp8_gemm_kernel(
    const __nv_fp8_e4m3* __restrict__ A, const __nv_fp8_e4m3* __restrict__ Bt,
    __nv_bfloat16* __restrict__ C, int K,
    const float* __restrict__ al, const float* __restrict__ ar,
    float* __restrict__ el, float* __restrict__ er)
{
    extern __shared__ char smem[];
    int tid = threadIdx.x;
    int lane = tid & 31, wid = tid >> 5;
    int wm = (wid & 1) * 64, wn = (wid >> 1) * 32;
    int g = lane >> 2, tig = lane & 3;
    const __nv_fp8_e4m3* Ab = A + (size_t)blockIdx.y * 128 * K;
    const __nv_fp8_e4m3* Bb = Bt + (size_t)blockIdx.x * 128 * K;

    unsigned sbase = (unsigned)__cvta_generic_to_shared(smem);
    unsigned aoff = (unsigned)((wm + (lane & 15)) * 80 + (lane >> 4) * 16);
    unsigned boff = (unsigned)((wn + ((lane >> 4) & 1) * 8 + (lane & 7)) * 80
                               + ((lane >> 3) & 1) * 16);

    float c[4][4][4];
#pragma unroll
    for (int mt = 0; mt < 4; mt++)
#pragma unroll
        for (int nt = 0; nt < 4; nt++)
#pragma unroll
            for (int i = 0; i < 4; i++) c[mt][nt][i] = 0.f;

    int nk = K / BK8;                    // >= 12 always
    fp8_load_tiles(smem, Ab, Bb, 0, 0, tid, K);
    asm volatile("cp.async.commit_group;");
    fp8_load_tiles(smem, Ab, Bb, 1, BK8, tid, K);
    asm volatile("cp.async.commit_group;");

    int stage = 0;
    for (int t = 0; t < nk; t++) {
        asm volatile("cp.async.wait_group 1;" ::: "memory");
        __syncthreads();
        // prefetch t+2 into the stage freed at t-1 (safe: all threads passed it)
        if (t + 2 < nk) {
            int st2 = stage + 2; if (st2 >= 3) st2 -= 3;
            fp8_load_tiles(smem, Ab, Bb, st2, (t + 2) * BK8, tid, K);
        }
        asm volatile("cp.async.commit_group;");

        unsigned sa = sbase + (unsigned)(stage * STAGE_B);
        unsigned sb = sa + (unsigned)(128 * 80);
#pragma unroll
        for (int kk2 = 0; kk2 < 2; kk2++) {
            unsigned a[4][4], b[4][2];
#pragma unroll
            for (int mt = 0; mt < 4; mt++)
                LDSM4(a[mt][0], a[mt][1], a[mt][2], a[mt][3],
                      sa + aoff + (unsigned)(mt * 16 * 80 + kk2 * 32));
#pragma unroll
            for (int ntp = 0; ntp < 2; ntp++)
                LDSM4(b[ntp * 2][0], b[ntp * 2][1], b[ntp * 2 + 1][0], b[ntp * 2 + 1][1],
                      sb + boff + (unsigned)(ntp * 16 * 80 + kk2 * 32));
#pragma unroll
            for (int mt = 0; mt < 4; mt++)
#pragma unroll
                for (int nt = 0; nt < 4; nt++)
                    asm volatile(
                        "mma.sync.aligned.m16n8k32.row.col.f32.e4m3.e4m3.f32 "
                        "{%0,%1,%2,%3}, {%4,%5,%6,%7}, {%8,%9}, {%0,%1,%2,%3};"
                        : "+f"(c[mt][nt][0]), "+f"(c[mt][nt][1]),
                          "+f"(c[mt][nt][2]), "+f"(c[mt][nt][3])
                        : "r"(a[mt][0]), "r"(a[mt][1]), "r"(a[mt][2]), "r"(a[mt][3]),
                          "r"(b[nt][0]), "r"(b[nt][1]));
        }
        __syncthreads();
        if (++stage == 3) stage = 0;
    }

    // ---- epilogue: bf16 store + fused el/er partial dots ----
    __nv_bfloat16* Cb = C + (size_t)(blockIdx.y * 128) * NHD + blockIdx.x * 128;
    float pel[8], per[8];
#pragma unroll
    for (int i = 0; i < 8; i++) { pel[i] = 0.f; per[i] = 0.f; }
#pragma unroll
    for (int nt = 0; nt < 4; nt++) {
        int colg = blockIdx.x * 128 + wn + nt * 8 + 2 * tig;
        float a0 = al[colg], a1 = al[colg + 1];
        float r0 = ar[colg], r1 = ar[colg + 1];
#pragma unroll
        for (int mt = 0; mt < 4; mt++) {
            int row = wm + mt * 16 + g;
            int col = wn + nt * 8 + 2 * tig;
            *(__nv_bfloat162*)(Cb + (size_t)row * NHD + col) =
                __floats2bfloat162_rn(c[mt][nt][0], c[mt][nt][1]);
            *(__nv_bfloat162*)(Cb + (size_t)(row + 8) * NHD + col) =
                __floats2bfloat162_rn(c[mt][nt][2], c[mt][nt][3]);
            pel[mt * 2]     += c[mt][nt][0] * a0 + c[mt][nt][1] * a1;
            pel[mt * 2 + 1] += c[mt][nt][2] * a0 + c[mt][nt][3] * a1;
            per[mt * 2]     += c[mt][nt][0] * r0 + c[mt][nt][1] * r1;
            per[mt * 2 + 1] += c[mt][nt][2] * r0 + c[mt][nt][3] * r1;
        }
    }
#pragma unroll
    for (int off = 1; off <= 2; off <<= 1)
#pragma unroll
        for (int i = 0; i < 8; i++) {
            pel[i] += __shfl_xor_sync(0xffffffffu, pel[i], off);
            per[i] += __shfl_xor_sync(0xffffffffu, per[i], off);
        }
    if (tig == 0) {
        int hd = (blockIdx.x * 128) / NF;
#pragma unroll
        for (int mt = 0; mt < 4; mt++)
#pragma unroll
            for (int hf = 0; hf < 2; hf++) {
                int n = blockIdx.y * 128 + wm + mt * 16 + hf * 8 + g;
                atomicAdd(&el[n * NH + hd], pel[mt * 2 + hf]);
                atomicAdd(&er[n * NH + hd], per[mt * 2 + hf]);
            }
    }
}

// ---------------- fp32 -> fp8 convert ----------------
__global__ void cvt8_kernel(const float* __restrict__ x, __nv_fp8_e4m3* __restrict__ o, int n) {
    int i = blockIdx.x * 256 + threadIdx.x;
    if (i < n) o[i] = __nv_fp8_e4m3(x[i]);
}

// ---------------- W[K][M] -> Bt[M][K] fp8 transpose ----------------
__global__ __launch_bounds__(256) void wtrans_kernel(
    const float* __restrict__ W, __nv_fp8_e4m3* __restrict__ Bt, int K, int M)
{
    __shared__ float t[32][33];
    int m0 = blockIdx.x * 32, k0 = blockIdx.y * 32;
    int tx = threadIdx.x & 31, ty = threadIdx.x >> 5;
#pragma unroll
    for (int i = 0; i < 32; i += 8)
        t[ty + i][tx] = W[(size_t)(k0 + ty + i) * M + m0 + tx];
    __syncthreads();
#pragma unroll
    for (int i = 0; i < 32; i += 8)
        Bt[(size_t)(m0 + ty + i) * K + k0 + tx] = __nv_fp8_e4m3(t[tx][ty + i]);
}

// ---------------- per-layer zeroing ----------------
__global__ void prep_kernel() {
    int i = blockIdx.x * 256 + threadIdx.x;
    if (i < NHD) { g_colsum[i] = 0.f; g_colsq[i] = 0.f; }
    if (i < NN * NH) { g_el[i] = 0.f; g_er[i] = 0.f; }
}

// ---------------- edge softmax + aggregation (+bias), bf16 ----------------
__global__ __launch_bounds__(256) void aggregate_kernel(
    const __nv_bfloat16* __restrict__ feat, const float* __restrict__ el,
    const float* __restrict__ er, const int* __restrict__ esrc,
    const float* __restrict__ bias, __nv_bfloat16* __restrict__ outh)
{
    int n = blockIdx.x;
    __shared__ int   ssrc[DEG];
    __shared__ float salpha[NH * DEG];
    int tid = threadIdx.x;
    if (tid < DEG) ssrc[tid] = esrc[n * DEG + tid];
    __syncthreads();
    if (tid < 32) {
        int h = tid >> 3, k = tid & 7;
        float e = el[ssrc[k] * NH + h] + er[n * NH + h];
        e = e > 0.f ? e : 0.2f * e;
        float m = e;
#pragma unroll
        for (int o = 4; o; o >>= 1) m = fmaxf(m, __shfl_xor_sync(0xffffffffu, m, o));
        float a = __expf(e - m);
        float s = a;
#pragma unroll
        for (int o = 4; o; o >>= 1) s += __shfl_xor_sync(0xffffffffu, s, o);
        salpha[tid] = a / s;
    }
    __syncthreads();
    const __nv_bfloat162* f2 = (const __nv_bfloat162*)feat;
    __nv_bfloat162* o2 = (__nv_bfloat162*)outh;
    for (int c2 = tid; c2 < NHD / 2; c2 += 256) {
        int h = c2 / (NF / 2);
        float accx = bias[2 * c2], accy = bias[2 * c2 + 1];
#pragma unroll
        for (int k = 0; k < DEG; k++) {
            float w = salpha[h * DEG + k];
            float2 v = __bfloat1622float2(f2[(size_t)ssrc[k] * (NHD / 2) + c2]);
            accx += w * v.x; accy += w * v.y;
        }
        o2[(size_t)n * (NHD / 2) + c2] = __floats2bfloat162_rn(accx, accy);
    }
}

// ---------------- column stats ----------------
__global__ __launch_bounds__(256) void colstats_kernel(const __nv_bfloat16* __restrict__ x) {
    int c2 = blockIdx.x * 256 + threadIdx.x;
    int r0 = blockIdx.y * 256;
    const __nv_bfloat162* x2 = (const __nv_bfloat162*)x;
    float s0 = 0.f, s1 = 0.f, q0 = 0.f, q1 = 0.f;
    for (int r = r0; r < r0 + 256; r++) {
        float2 v = __bfloat1622float2(x2[(size_t)r * (NHD / 2) + c2]);
        s0 += v.x; q0 += v.x * v.x;
        s1 += v.y; q1 += v.y * v.y;
    }
    atomicAdd(&g_colsum[2 * c2], s0);
    atomicAdd(&g_colsum[2 * c2 + 1], s1);
    atomicAdd(&g_colsq[2 * c2], q0);
    atomicAdd(&g_colsq[2 * c2 + 1], q1);
}

__global__ void colfin_kernel(const float* __restrict__ gamma, const float* __restrict__ beta) {
    int c = blockIdx.x * 256 + threadIdx.x;
    if (c >= NHD) return;
    float mu  = g_colsum[c] * (1.f / NN);
    float var = g_colsq[c] * (1.f / NN) - mu * mu;
    float rs  = rsqrtf(var + 1e-5f);
    float a   = rs * gamma[c];
    g_colA[c] = a;
    g_colB[c] = beta[c] - mu * a;
}

// ---------------- LN + PReLU epilogues ----------------
__global__ __launch_bounds__(256) void lnfuse1_kernel(
    const __nv_bfloat16* __restrict__ h, const float* __restrict__ pa,
    __nv_fp8_e4m3* __restrict__ a8, float* __restrict__ m1)
{
    int n = blockIdx.x;
    for (int f = threadIdx.x; f < NF; f += 256) {
        float s = 0.f;
#pragma unroll
        for (int hh = 0; hh < 4; hh++) {
            int c = hh * NF + f;
            float y = g_colA[c] * __bfloat162float(h[(size_t)n * NHD + c]) + g_colB[c];
            y = y > 0.f ? y : pa[c] * y;
            a8[(size_t)n * NHD + c] = __nv_fp8_e4m3(y);
            s += y;
        }
        m1[(size_t)n * NF + f] = 0.25f * s;
    }
}

__global__ __launch_bounds__(256) void lnfuse2_kernel(
    const __nv_bfloat16* __restrict__ h, const float* __restrict__ pa)
{
    int n = blockIdx.x;
    for (int f = threadIdx.x; f < NF; f += 256) {
        float s = 0.f;
#pragma unroll
        for (int hh = 0; hh < 4; hh++) {
            int c = hh * NF + f;
            float y = g_colA[c] * __bfloat162float(h[(size_t)n * NHD + c]) + g_colB[c];
            y = y > 0.f ? y : pa[c] * y;
            s += y;
        }
        g_rep[(size_t)n * NF + f] = fmaxf(g_m1[(size_t)n * NF + f], 0.25f * s);
    }
}

// ---------------- sims: S[128 x 8192] = Qe @ rep^T ----------------
__global__ __launch_bounds__(256) void simgemm_kernel(
    const float* __restrict__ Qe, const float* __restrict__ R)
{
    __shared__ float Qs[128][33];
    __shared__ float Rs[32][33];
    int tid = threadIdx.x;
    int n0 = blockIdx.x * 32;
    float acc[16];
#pragma unroll
    for (int i = 0; i < 16; i++) acc[i] = 0.f;
    int n = tid & 31, rb = tid >> 5;

    for (int k0 = 0; k0 < ND; k0 += 32) {
#pragma unroll
        for (int t = 0; t < 16; t++) {
            int li = tid + t * 256;
            Qs[li >> 5][li & 31] = Qe[(size_t)(li >> 5) * ND + k0 + (li & 31)];
        }
#pragma unroll
        for (int t = 0; t < 4; t++) {
            int li = tid + t * 256;
            Rs[li >> 5][li & 31] = R[(size_t)(n0 + (li >> 5)) * ND + k0 + (li & 31)];
        }
        __syncthreads();
#pragma unroll
        for (int kk = 0; kk < 32; kk++) {
            float b = Rs[n][kk];
#pragma unroll
            for (int i = 0; i < 16; i++)
                acc[i] += Qs[rb + 8 * i][kk] * b;
        }
        __syncthreads();
    }
#pragma unroll
    for (int i = 0; i < 16; i++)
        g_S[(size_t)(rb + 8 * i) * NN + n0 + n] = acc[i];
}

// ---------------- output zero ----------------
__global__ void zeroout_kernel(float* out) {
    if (threadIdx.x < 3) out[threadIdx.x] = 0.f;
}

// ---------------- losses ----------------
__device__ __forceinline__ float warpSumF(float v) {
#pragma unroll
    for (int o = 16; o; o >>= 1) v += __shfl_xor_sync(0xffffffffu, v, o);
    return v;
}

__device__ __forceinline__ float blockSumF(float v, float* sred, int tid) {
    v = warpSumF(v);
    if ((tid & 31) == 0) sred[tid >> 5] = v;
    __syncthreads();
    if (tid < 32) {
        float x = (tid < 16) ? sred[tid] : 0.f;
        x = warpSumF(x);
        if (tid == 0) sred[0] = x;
    }
    __syncthreads();
    float r = sred[0];
    __syncthreads();
    return r;
}

__device__ __forceinline__ float blockMaxF(float v, float* sred, int tid) {
#pragma unroll
    for (int o = 16; o; o >>= 1) v = fmaxf(v, __shfl_xor_sync(0xffffffffu, v, o));
    if ((tid & 31) == 0) sred[tid >> 5] = v;
    __syncthreads();
    if (tid < 32) {
        float x = (tid < 16) ? sred[tid] : -INFINITY;
#pragma unroll
        for (int o = 16; o; o >>= 1) x = fmaxf(x, __shfl_xor_sync(0xffffffffu, x, o));
        if (tid == 0) sred[0] = x;
    }
    __syncthreads();
    float r = sred[0];
    __syncthreads();
    return r;
}

__device__ void bitonic1024_desc(float* key, int* idx, int tid) {
    for (int k = 2; k <= 1024; k <<= 1) {
        for (int j = k >> 1; j > 0; j >>= 1) {
#pragma unroll 1
            for (int t = tid; t < 1024; t += 512) {
                int x = t ^ j;
                if (x > t) {
                    bool descSeg = ((t & k) == 0);
                    float ka = key[t], kb = key[x];
                    int   ia = idx[t], ib = idx[x];
                    bool aFirst = (ka > kb) || (ka == kb && ia < ib);
                    bool doSwap = descSeg ? (!aFirst) : aFirst;
                    if (doSwap) { key[t] = kb; key[x] = ka; idx[t] = ib; idx[x] = ia; }
                }
            }
            __syncthreads();
        }
    }
}

// lambda-MRR via product trick (no per-pair MUFU).
__global__ __launch_bounds__(512) void loss_kernel(const float* __restrict__ bert, float* __restrict__ out) {
    __shared__ float skey[1024];
    __shared__ int   sidx[1024];
    __shared__ float sez[1024];
    __shared__ float sred[16];
    __shared__ float sh_psim;
    int r = blockIdx.x;
    int g = r >> 4;
    int base = g * NPG;
    int tid = threadIdx.x;
    const float* Srow = g_S + (size_t)r * NN;

    skey[tid]       = bert[(size_t)r * NPG + tid];       sidx[tid]       = tid;
    skey[tid + 512] = bert[(size_t)r * NPG + tid + 512]; sidx[tid + 512] = tid + 512;
    __syncthreads();
    bitonic1024_desc(skey, sidx, tid);

    int i0 = sidx[tid], i1 = sidx[tid + 512];
    float v0 = Srow[base + i0], v1 = Srow[base + i1];
    __syncthreads();
    skey[tid] = v0;       sidx[tid] = tid;
    skey[tid + 512] = v1; sidx[tid + 512] = tid + 512;
    if (tid == 0) sh_psim = v0;
    __syncthreads();

    bitonic1024_desc(skey, sidx, tid);

    {
        float y0 = skey[0];
        sez[tid]       = __expf(fmaxf(skey[tid]       - y0, -60.f));
        sez[tid + 512] = __expf(fmaxf(skey[tid + 512] - y0, -60.f));
    }
    __syncthreads();

    int wid = tid >> 5, lane = tid & 31;
    float uacc = 0.f, tacc = 0.f;
#pragma unroll 1
    for (int half = 0; half < 2; half++) {
        int c = half ? (31 - wid) : wid;
        int i = c * 32 + lane;
        float yi = skey[i];
        int   pi = sidx[i];
        float inv = __fdividef(1.f, sez[i]);
        float ts0 = 0.f, ts1 = 0.f, ts2 = 0.f, ts3 = 0.f;
#pragma unroll 1
        for (int jb = c * 32; jb < 1024; jb += 32) {
            float p0 = 1.f, p1 = 1.f, p2 = 1.f, p3 = 1.f;
#pragma unroll
            for (int q4 = 0; q4 < 8; q4++) {
                int j4 = jb + q4 * 4;
                float4 y4 = *(const float4*)&skey[j4];
                float4 e4 = *(const float4*)&sez[j4];
                int4   p4 = *(const int4*)&sidx[j4];
                {   bool act = (j4 + 0) > i;
                    p0 *= act ? fmaf(e4.x, inv, 1.f) : 1.f;
                    float t = fminf(yi - y4.x, 50.f);
                    if (act && pi > p4.x) ts0 += t; }
                {   bool act = (j4 + 1) > i;
                    p1 *= act ? fmaf(e4.y, inv, 1.f) : 1.f;
                    float t = fminf(yi - y4.y, 50.f);
                    if (act && pi > p4.y) ts1 += t; }
                {   bool act = (j4 + 2) > i;
                    p2 *= act ? fmaf(e4.z, inv, 1.f) : 1.f;
                    float t = fminf(yi - y4.z, 50.f);
                    if (act && pi > p4.z) ts2 += t; }
                {   bool act = (j4 + 3) > i;
                    p3 *= act ? fmaf(e4.w, inv, 1.f) : 1.f;
                    float t = fminf(yi - y4.w, 50.f);
                    if (act && pi > p4.w) ts3 += t; }
            }
            uacc += __logf((p0 * p1) * (p2 * p3));
        }
        tacc += (ts0 + ts1) + (ts2 + ts3);
    }
    float Ltot = blockSumF(uacc + tacc, sred, tid);

    float mx = -INFINITY;
    for (int c = tid; c < NN; c += 512) mx = fmaxf(mx, Srow[c]);
    float m = blockMaxF(mx, sred, tid);

    float se = 0.f, s1 = 0.f, s2 = 0.f;
    for (int c = tid; c < NN; c += 512) {
        float x = Srow[c] - m;
        float e = __expf(x);
        se += e;
        if (c >= base && c < base + NPG) { s1 += e; s2 += x * e; }
    }
    se = blockSumF(se, sred, tid);
    s1 = blockSumF(s1, sred, tid);
    s2 = blockSumF(s2, sred, tid);

    if (tid == 0) {
        float lse = m + __logf(se);
        float cl  = lse - sh_psim;
        float ent = __logf(s1) - s2 / s1;
        atomicAdd(out + 0, cl  * (1.f / 128.f));
        atomicAdd(out + 2, ent * (1.f / 128.f));
        atomicAdd(out + 1, Ltot * (1.f / 67043328.f));
    }
}

// ---------------- launch ----------------
extern "C" void kernel_launch(void* const* d_in, const int* in_sizes, int n_in,
                              void* d_out, int out_size) {
    const float* x      = (const float*)d_in[0];
    const int*   esrc   = (const int*)d_in[1];
    const float* qe     = (const float*)d_in[3];
    const float* bert   = (const float*)d_in[4];
    const float* W1     = (const float*)d_in[5];
    const float* al1    = (const float*)d_in[6];
    const float* ar1    = (const float*)d_in[7];
    const float* b1     = (const float*)d_in[8];
    const float* gamma1 = (const float*)d_in[9];
    const float* beta1  = (const float*)d_in[10];
    const float* pa1    = (const float*)d_in[11];
    const float* W2     = (const float*)d_in[12];
    const float* al2    = (const float*)d_in[13];
    const float* ar2    = (const float*)d_in[14];
    const float* b2     = (const float*)d_in[15];
    const float* gamma2 = (const float*)d_in[16];
    const float* beta2  = (const float*)d_in[17];
    const float* pa2    = (const float*)d_in[18];
    float* out = (float*)d_out;

    float *el, *er, *m1, *rep;
    __nv_bfloat16 *feat16, *h16;
    __nv_fp8_e4m3 *a8, *bT8;
    cudaGetSymbolAddress((void**)&feat16, g_feat16);
    cudaGetSymbolAddress((void**)&h16,    g_h16);
    cudaGetSymbolAddress((void**)&el,     g_el);
    cudaGetSymbolAddress((void**)&er,     g_er);
    cudaGetSymbolAddress((void**)&m1,     g_m1);
    cudaGetSymbolAddress((void**)&rep,    g_rep);
    cudaGetSymbolAddress((void**)&a8,     g_a8);
    cudaGetSymbolAddress((void**)&bT8,    g_bT8);

    cudaFuncSetAttribute(fp8_gemm_kernel,
                         cudaFuncAttributeMaxDynamicSharedMemorySize, GEMM_SMEM);

    dim3 gGemm(NHD / 128, NN / 128);       // (24, 64)
    dim3 gStats(NHD / 512, NN / 256);      // (6, 32)

    // ---- layer 1 (ncu -s5 slot lands on fp8_gemm_kernel) ----
    cvt8_kernel<<<(NN * ND + 255) / 256, 256>>>(x, a8, NN * ND);
    wtrans_kernel<<<dim3(NHD / 32, ND / 32), 256>>>(W1, bT8, ND, NHD);
    prep_kernel<<<(NN * NH + 255) / 256, 256>>>();
    fp8_gemm_kernel<<<gGemm, 256, GEMM_SMEM>>>(a8, bT8, feat16, ND, al1, ar1, el, er);
    aggregate_kernel<<<NN, 256>>>(feat16, el, er, esrc, b1, h16);
    colstats_kernel<<<gStats, 256>>>(h16);
    colfin_kernel<<<NHD / 256, 256>>>(gamma1, beta1);
    lnfuse1_kernel<<<NN, 256>>>(h16, pa1, a8, m1);

    // ---- layer 2 ----
    wtrans_kernel<<<dim3(NHD / 32, NHD / 32), 256>>>(W2, bT8, NHD, NHD);
    prep_kernel<<<(NN * NH + 255) / 256, 256>>>();
    fp8_gemm_kernel<<<gGemm, 256, GEMM_SMEM>>>(a8, bT8, feat16, NHD, al2, ar2, el, er);
    aggregate_kernel<<<NN, 256>>>(feat16, el, er, esrc, b2, h16);
    colstats_kernel<<<gStats, 256>>>(h16);
    colfin_kernel<<<NHD / 256, 256>>>(gamma2, beta2);
    lnfuse2_kernel<<<NN, 256>>>(h16, pa2);

    // ---- similarities + losses ----
    simgemm_kernel<<<NN / 32, 256>>>(qe, rep);
    zeroout_kernel<<<1, 32>>>(out);
    loss_kernel<<<NROW, 512>>>(bert, out);
}